// round 15
// baseline (speedup 1.0000x reference)
#include <cuda_runtime.h>
#include <cuda_bf16.h>
#include <cstdint>
#include <cstddef>

#define S_  2048
#define D_  64
#define H_  16
#define B_  2
#define BH_ 32
#define TQ  128
#define TK  64
#define NKT (S_/TK)      /* 32 */

// ---------------- device scratch (allocation-free rule) ----------------
__device__ __nv_bfloat16 g_qhi[BH_*S_*D_], g_qlo[BH_*S_*D_];
__device__ __nv_bfloat16 g_khi[BH_*S_*D_], g_klo[BH_*S_*D_];
__device__ __nv_bfloat16 g_vthi[BH_*D_*S_], g_vtlo[BH_*D_*S_];   // V^T: [bh][d][k]

// ---------------- helpers ----------------
__device__ __forceinline__ unsigned smem_u32(const void* p){
    unsigned a;
    asm("{ .reg .u64 t; cvta.to.shared.u64 t, %1; cvt.u32.u64 %0, t; }":"=r"(a):"l"(p));
    return a;
}
__device__ __forceinline__ void ldsm_x4(unsigned& a0,unsigned& a1,unsigned& a2,unsigned& a3, unsigned addr){
    asm volatile("ldmatrix.sync.aligned.m8n8.x4.shared.b16 {%0,%1,%2,%3}, [%4];"
        : "=r"(a0),"=r"(a1),"=r"(a2),"=r"(a3) : "r"(addr));
}
__device__ __forceinline__ void ldsm_x2(unsigned& b0,unsigned& b1, unsigned addr){
    asm volatile("ldmatrix.sync.aligned.m8n8.x2.shared.b16 {%0,%1}, [%2];"
        : "=r"(b0),"=r"(b1) : "r"(addr));
}
__device__ __forceinline__ void mma16816(float* c, unsigned a0,unsigned a1,unsigned a2,unsigned a3,
                                         unsigned b0,unsigned b1){
    asm volatile("mma.sync.aligned.m16n8k16.row.col.f32.bf16.bf16.f32 "
        "{%0,%1,%2,%3}, {%4,%5,%6,%7}, {%8,%9}, {%0,%1,%2,%3};"
        : "+f"(c[0]),"+f"(c[1]),"+f"(c[2]),"+f"(c[3])
        : "r"(a0),"r"(a1),"r"(a2),"r"(a3),"r"(b0),"r"(b1));
}
__device__ __forceinline__ void cp16(unsigned saddr, const void* g){
    asm volatile("cp.async.cg.shared.global [%0], [%1], 16;" :: "r"(saddr), "l"(g));
}
#define CP_COMMIT() asm volatile("cp.async.commit_group;" ::: "memory")
#define CP_WAIT(n)  asm volatile("cp.async.wait_group %0;" :: "n"(n) : "memory")

// pack two floats -> bf16x2 hi and bf16x2 lo-residual
__device__ __forceinline__ void hilo2(float a, float b, unsigned& h, unsigned& lo){
    __nv_bfloat16 ha = __float2bfloat16(a), hb = __float2bfloat16(b);
    h  = ((unsigned)__bfloat16_as_ushort(hb) << 16) | (unsigned)__bfloat16_as_ushort(ha);
    __nv_bfloat16 la = __float2bfloat16(a - __bfloat162float(ha));
    __nv_bfloat16 lb = __float2bfloat16(b - __bfloat162float(hb));
    lo = ((unsigned)__bfloat16_as_ushort(lb) << 16) | (unsigned)__bfloat16_as_ushort(la);
}

// ---------------- prep: Q,K elementwise hi/lo; V transpose hi/lo ----------------
__global__ __launch_bounds__(256) void prep_kernel(
    const float* __restrict__ Q, const float* __restrict__ K, const float* __restrict__ V)
{
    const int tid = threadIdx.x, bh = blockIdx.y, z = blockIdx.z;
    if (z < 2){
        const float* src = z ? K : Q;
        __nv_bfloat16* dh = z ? g_khi : g_qhi;
        __nv_bfloat16* dl = z ? g_klo : g_qlo;
        size_t base = ((size_t)bh*S_ + blockIdx.x*64)*D_;
        #pragma unroll
        for (int it = 0; it < 8; ++it){
            int i2 = it*256 + tid;
            float2 v = *(const float2*)(src + base + i2*2);
            __nv_bfloat16 h0 = __float2bfloat16(v.x), h1 = __float2bfloat16(v.y);
            __nv_bfloat162 hh; hh.x = h0; hh.y = h1;
            __nv_bfloat162 ll;
            ll.x = __float2bfloat16(v.x - __bfloat162float(h0));
            ll.y = __float2bfloat16(v.y - __bfloat162float(h1));
            *(__nv_bfloat162*)(dh + base + i2*2) = hh;
            *(__nv_bfloat162*)(dl + base + i2*2) = ll;
        }
    } else {
        __shared__ float ts[64][69];
        const int k0 = blockIdx.x * 64;
        #pragma unroll
        for (int it = 0; it < 16; ++it){
            int lin = it*256 + tid;
            int kk = lin >> 6, d = lin & 63;
            ts[kk][d] = V[((size_t)bh*S_ + k0 + kk)*D_ + d];
        }
        __syncthreads();
        #pragma unroll
        for (int it = 0; it < 16; ++it){
            int lin = it*256 + tid;
            int d = lin >> 6, kk = lin & 63;
            float v = ts[kk][d];
            __nv_bfloat16 h = __float2bfloat16(v);
            __nv_bfloat16 l = __float2bfloat16(v - __bfloat162float(h));
            size_t o = ((size_t)bh*D_ + d)*S_ + k0 + kk;
            g_vthi[o] = h;
            g_vtlo[o] = l;
        }
    }
}

// ---------------- fused attention (TK=64, 2 CTAs/SM) ----------------
// All tiles use 64-elem rows with stride SQ1=72 elems (144B => +4 banks/row).
#define SQ1   72
#define F_QH  0
#define F_QL  18432
#define F_KH  36864
#define F_KL  46080
#define F_VH  55296
#define F_VL  64512
#define F_MT  73728     /* per-tile row max: [32][128] fp32 = 16384 */
#define F_MS  90112     /* final m per row: 512 */
#define F_IL  90624     /* 1/l per row: 512 */
#define SMEMF 91136

__global__ __launch_bounds__(256, 2) void fused_attn_kernel(
    const unsigned* __restrict__ mask, const float* __restrict__ adj,
    float* __restrict__ P, float* __restrict__ Out)
{
    extern __shared__ char smem[];
    const unsigned sb = smem_u32(smem);
    const int tid = threadIdx.x, w = tid >> 5, l = tid & 31;
    const int bh = blockIdx.y, b = bh >> 4;
    const int q0 = blockIdx.x * TQ;

    // prologue: Q hi/lo via cp.async
    {
        const __nv_bfloat16* qh = g_qhi + ((size_t)bh*S_ + q0)*D_;
        const __nv_bfloat16* ql = g_qlo + ((size_t)bh*S_ + q0)*D_;
        #pragma unroll
        for (int it = 0; it < 8; ++it){
            int lin = it*256 + tid;           // 0..2047
            int half = lin >> 10, idx = lin & 1023;
            int row = idx >> 3, g = idx & 7;
            cp16(sb + (half ? F_QL : F_QH) + (row*SQ1 + g*8)*2,
                 (half ? ql : qh) + row*D_ + g*8);
        }
        CP_COMMIT();
    }

    const __nv_bfloat16* kh_g = g_khi + (size_t)bh*S_*D_;
    const __nv_bfloat16* kl_g = g_klo + (size_t)bh*S_*D_;
    const __nv_bfloat16* vh_g = g_vthi + (size_t)bh*D_*S_;
    const __nv_bfloat16* vl_g = g_vtlo + (size_t)bh*D_*S_;

    const int la_row = 16*w + (l & 15);
    const int la_k8  = (l >> 4) * 8;
    const int lb_row = l & 7;
    const int lb_k8  = ((l >> 3) & 1) * 8;
    const int qr = l >> 2;
    const int ci = l & 3;

    float m_run[2] = {-3.0e38f, -3.0e38f};
    float l_run[2] = {0.f, 0.f};
    float oacc[8][4];
    #pragma unroll
    for (int dg = 0; dg < 8; ++dg)
        #pragma unroll
        for (int j = 0; j < 4; ++j) oacc[dg][j] = 0.f;

    float* sm_mt = (float*)(smem + F_MT);

    for (int kt = 0; kt < NKT; ++kt){
        const int k0 = kt * TK;
        // K tile hi/lo: [64 rows][64 d]   (1024 cp16 per buffer-half total 1024)
        // V^T tile hi/lo: [64 d][64 k]
        {
            int lin = tid;                    // 1024 total chunks over 4 iters
            #pragma unroll
            for (int it = 0; it < 4; ++it, lin += 256){
                int half = (lin >> 9) & 1;    // 0: hi, 1: lo
                int idx = lin & 511;
                int row = idx >> 3, g = idx & 7;
                cp16(sb + (half ? F_KL : F_KH) + (row*SQ1 + g*8)*2,
                     (half ? kl_g : kh_g) + (size_t)(k0 + row)*D_ + g*8);
            }
            lin = tid;
            #pragma unroll
            for (int it = 0; it < 4; ++it, lin += 256){
                int half = (lin >> 9) & 1;
                int idx = lin & 511;
                int row = idx >> 3, g = idx & 7;   // row = d, g*8 = k chunk
                cp16(sb + (half ? F_VL : F_VH) + (row*SQ1 + g*8)*2,
                     (half ? vl_g : vh_g) + (size_t)row*S_ + k0 + g*8);
            }
        }
        CP_COMMIT(); CP_WAIT(0);
        __syncthreads();

        // ---- QK^T (64 cols) ----
        float acc[8][4];
        #pragma unroll
        for (int nt = 0; nt < 8; ++nt)
            #pragma unroll
            for (int j = 0; j < 4; ++j) acc[nt][j] = 0.f;

        #pragma unroll
        for (int kk = 0; kk < 4; ++kk){
            const int koffA = kk*16 + la_k8;
            unsigned ah0,ah1,ah2,ah3, al0,al1,al2,al3;
            ldsm_x4(ah0,ah1,ah2,ah3, sb + F_QH + (la_row*SQ1 + koffA)*2);
            ldsm_x4(al0,al1,al2,al3, sb + F_QL + (la_row*SQ1 + koffA)*2);
            const int koffB = kk*16 + lb_k8;
            #pragma unroll
            for (int nt = 0; nt < 8; ++nt){
                unsigned bh0,bh1, bl0,bl1;
                ldsm_x2(bh0,bh1, sb + F_KH + ((8*nt + lb_row)*SQ1 + koffB)*2);
                ldsm_x2(bl0,bl1, sb + F_KL + ((8*nt + lb_row)*SQ1 + koffB)*2);
                mma16816(acc[nt], ah0,ah1,ah2,ah3, bh0,bh1);
                mma16816(acc[nt], ah0,ah1,ah2,ah3, bl0,bl1);
                mma16816(acc[nt], al0,al1,al2,al3, bh0,bh1);
            }
        }

        // ---- epilogue: bias+scale+mask, online (m,l), u=exp(s-m_kt), O rescale ----
        float e0[8], e1[8], f0[8], f1[8];
        #pragma unroll
        for (int h = 0; h < 2; ++h){
            const int row = 16*w + qr + 8*h;
            const float2* ap = (const float2*)(adj + ((size_t)bh*S_ + q0 + row)*S_ + k0);
            const uint2*  mp = (const uint2*) (mask + ((size_t)b*S_  + q0 + row)*S_ + k0);
            float2*       pp = (float2*)(P + ((size_t)bh*S_ + q0 + row)*S_ + k0);
            float* u0 = h ? f0 : e0;
            float* u1 = h ? f1 : e1;
            float pm = -3.0e38f;
            #pragma unroll
            for (int nt = 0; nt < 8; ++nt){
                float2 a = ap[ci + 4*nt];
                uint2 mv = mp[ci + 4*nt];
                float x0 = (acc[nt][2*h]   + a.x) * 0.125f;
                float x1 = (acc[nt][2*h+1] + a.y) * 0.125f;
                if (mv.x) x0 = __int_as_float(0xff800000u);
                if (mv.y) x1 = __int_as_float(0xff800000u);
                u0[nt] = x0; u1[nt] = x1;
                pm = fmaxf(pm, fmaxf(x0, x1));
            }
            pm = fmaxf(pm, __shfl_xor_sync(0xffffffffu, pm, 1));
            pm = fmaxf(pm, __shfl_xor_sync(0xffffffffu, pm, 2));
            float mn = fmaxf(m_run[h], pm);
            float corr = __expf(m_run[h] - mn);
            float es = 0.f;
            #pragma unroll
            for (int nt = 0; nt < 8; ++nt){
                u0[nt] = __expf(u0[nt] - mn);
                u1[nt] = __expf(u1[nt] - mn);
                es += u0[nt] + u1[nt];
            }
            es += __shfl_xor_sync(0xffffffffu, es, 1);
            es += __shfl_xor_sync(0xffffffffu, es, 2);
            l_run[h] = l_run[h]*corr + es;
            m_run[h] = mn;
            #pragma unroll
            for (int dg = 0; dg < 8; ++dg){
                oacc[dg][2*h]   *= corr;
                oacc[dg][2*h+1] *= corr;
            }
            #pragma unroll
            for (int nt = 0; nt < 8; ++nt)
                pp[ci + 4*nt] = make_float2(u0[nt], u1[nt]);
            if (ci == 0)
                sm_mt[kt*128 + row] = mn;
        }

        // ---- PV: O += u @ V  (u fragments straight from registers) ----
        #pragma unroll
        for (int kb = 0; kb < 4; ++kb){
            unsigned ah0,al0, ah1,al1, ah2,al2, ah3,al3;
            hilo2(e0[2*kb],   e1[2*kb],   ah0, al0);
            hilo2(f0[2*kb],   f1[2*kb],   ah1, al1);
            hilo2(e0[2*kb+1], e1[2*kb+1], ah2, al2);
            hilo2(f0[2*kb+1], f1[2*kb+1], ah3, al3);
            const int koffB = kb*16 + lb_k8;
            #pragma unroll
            for (int dg = 0; dg < 8; ++dg){
                unsigned vh0,vh1, vl0,vl1;
                ldsm_x2(vh0,vh1, sb + F_VH + ((8*dg + lb_row)*SQ1 + koffB)*2);
                ldsm_x2(vl0,vl1, sb + F_VL + ((8*dg + lb_row)*SQ1 + koffB)*2);
                mma16816(oacc[dg], ah0,ah1,ah2,ah3, vh0,vh1);
                mma16816(oacc[dg], ah0,ah1,ah2,ah3, vl0,vl1);
                mma16816(oacc[dg], al0,al1,al2,al3, vh0,vh1);
            }
        }
        __syncthreads();   // all smem consumers done before next tile's loads
    }

    // ---- write O = oacc / l ----
    #pragma unroll
    for (int h = 0; h < 2; ++h){
        const int row = 16*w + qr + 8*h;
        const float inv = 1.0f / l_run[h];
        float2* op = (float2*)(Out + ((size_t)bh*S_ + q0 + row)*D_);
        #pragma unroll
        for (int dg = 0; dg < 8; ++dg)
            op[ci + 4*dg] = make_float2(oacc[dg][2*h]*inv, oacc[dg][2*h+1]*inv);
    }

    // ---- publish m/il, then rescale this CTA's P stripe in place ----
    float* sm_m  = (float*)(smem + F_MS);
    float* sm_il = (float*)(smem + F_IL);
    if (ci == 0){
        #pragma unroll
        for (int h = 0; h < 2; ++h){
            const int row = 16*w + qr + 8*h;
            sm_m[row]  = m_run[h];
            sm_il[row] = 1.0f / l_run[h];
        }
    }
    __syncthreads();   // m/il + all P(u) gmem writes visible block-wide

    #pragma unroll
    for (int j = 0; j < 16; ++j){
        const int lr = 8*j + w;              // 0..127
        const float m  = sm_m[lr];
        const float il = sm_il[lr];
        float4* pr = (float4*)(P + ((size_t)bh*S_ + q0 + lr)*S_);
        #pragma unroll 4
        for (int c = 0; c < 16; ++c){
            int idx = c*32 + l;              // 0..511 float4s across the row
            int kt = idx >> 4;               // 64-col tile id (16 float4 per tile)
            float sc = __expf(sm_mt[kt*128 + lr] - m) * il;
            float4 v = pr[idx];
            v.x *= sc; v.y *= sc; v.z *= sc; v.w *= sc;
            pr[idx] = v;
        }
    }
}

// ---------------------------------------------------------------------------
extern "C" void kernel_launch(void* const* d_in, const int* in_sizes, int n_in,
                              void* d_out, int out_size) {
    const float*    Q    = (const float*)d_in[0];
    const float*    K    = (const float*)d_in[1];
    const float*    V    = (const float*)d_in[2];
    const unsigned* mask = (const unsigned*)d_in[3];
    const float*    adj  = (const float*)d_in[4];

    float* out = (float*)d_out;                       // (B,H,S,D)
    float* P   = out + (size_t)B_ * H_ * S_ * D_;     // (B,H,S,S)

    cudaFuncSetAttribute(fused_attn_kernel, cudaFuncAttributeMaxDynamicSharedMemorySize, SMEMF);

    prep_kernel<<<dim3(S_/64, BH_, 3), 256>>>(Q, K, V);
    fused_attn_kernel<<<dim3(S_/TQ, BH_), 256, SMEMF>>>(mask, adj, P, out);
}

// round 16
// speedup vs baseline: 1.1721x; 1.1721x over previous
#include <cuda_runtime.h>
#include <cuda_bf16.h>
#include <cstdint>
#include <cstddef>

#define S_  2048
#define D_  64
#define H_  16
#define B_  2
#define BH_ 32
#define TQ  128
#define TK  128
#define NKT (S_/TK)      /* 16 */

// ---------------- device scratch (allocation-free rule) ----------------
__device__ __nv_bfloat16 g_qhi[BH_*S_*D_], g_qlo[BH_*S_*D_];
__device__ __nv_bfloat16 g_khi[BH_*S_*D_], g_klo[BH_*S_*D_];
__device__ __nv_bfloat16 g_vthi[BH_*D_*S_], g_vtlo[BH_*D_*S_];   // V^T: [bh][d][k]

// ---------------- helpers ----------------
__device__ __forceinline__ unsigned smem_u32(const void* p){
    unsigned a;
    asm("{ .reg .u64 t; cvta.to.shared.u64 t, %1; cvt.u32.u64 %0, t; }":"=r"(a):"l"(p));
    return a;
}
__device__ __forceinline__ void ldsm_x4(unsigned& a0,unsigned& a1,unsigned& a2,unsigned& a3, unsigned addr){
    asm volatile("ldmatrix.sync.aligned.m8n8.x4.shared.b16 {%0,%1,%2,%3}, [%4];"
        : "=r"(a0),"=r"(a1),"=r"(a2),"=r"(a3) : "r"(addr));
}
__device__ __forceinline__ void ldsm_x2(unsigned& b0,unsigned& b1, unsigned addr){
    asm volatile("ldmatrix.sync.aligned.m8n8.x2.shared.b16 {%0,%1}, [%2];"
        : "=r"(b0),"=r"(b1) : "r"(addr));
}
__device__ __forceinline__ void mma16816(float* c, unsigned a0,unsigned a1,unsigned a2,unsigned a3,
                                         unsigned b0,unsigned b1){
    asm volatile("mma.sync.aligned.m16n8k16.row.col.f32.bf16.bf16.f32 "
        "{%0,%1,%2,%3}, {%4,%5,%6,%7}, {%8,%9}, {%0,%1,%2,%3};"
        : "+f"(c[0]),"+f"(c[1]),"+f"(c[2]),"+f"(c[3])
        : "r"(a0),"r"(a1),"r"(a2),"r"(a3),"r"(b0),"r"(b1));
}
__device__ __forceinline__ void cp16(unsigned saddr, const void* g){
    asm volatile("cp.async.cg.shared.global [%0], [%1], 16;" :: "r"(saddr), "l"(g));
}
#define CP_COMMIT() asm volatile("cp.async.commit_group;" ::: "memory")
#define CP_WAIT(n)  asm volatile("cp.async.wait_group %0;" :: "n"(n) : "memory")

// pack two floats -> bf16x2 hi and bf16x2 lo-residual
__device__ __forceinline__ void hilo2(float a, float b, unsigned& h, unsigned& lo){
    __nv_bfloat16 ha = __float2bfloat16(a), hb = __float2bfloat16(b);
    h  = ((unsigned)__bfloat16_as_ushort(hb) << 16) | (unsigned)__bfloat16_as_ushort(ha);
    __nv_bfloat16 la = __float2bfloat16(a - __bfloat162float(ha));
    __nv_bfloat16 lb = __float2bfloat16(b - __bfloat162float(hb));
    lo = ((unsigned)__bfloat16_as_ushort(lb) << 16) | (unsigned)__bfloat16_as_ushort(la);
}

// ---------------- prep: Q,K elementwise hi/lo; V transpose hi/lo ----------------
__global__ __launch_bounds__(256) void prep_kernel(
    const float* __restrict__ Q, const float* __restrict__ K, const float* __restrict__ V)
{
    const int tid = threadIdx.x, bh = blockIdx.y, z = blockIdx.z;
    if (z < 2){
        const float* src = z ? K : Q;
        __nv_bfloat16* dh = z ? g_khi : g_qhi;
        __nv_bfloat16* dl = z ? g_klo : g_qlo;
        size_t base = ((size_t)bh*S_ + blockIdx.x*64)*D_;
        #pragma unroll
        for (int it = 0; it < 8; ++it){
            int i2 = it*256 + tid;
            float2 v = *(const float2*)(src + base + i2*2);
            __nv_bfloat16 h0 = __float2bfloat16(v.x), h1 = __float2bfloat16(v.y);
            __nv_bfloat162 hh; hh.x = h0; hh.y = h1;
            __nv_bfloat162 ll;
            ll.x = __float2bfloat16(v.x - __bfloat162float(h0));
            ll.y = __float2bfloat16(v.y - __bfloat162float(h1));
            *(__nv_bfloat162*)(dh + base + i2*2) = hh;
            *(__nv_bfloat162*)(dl + base + i2*2) = ll;
        }
    } else {
        __shared__ float ts[64][69];
        const int k0 = blockIdx.x * 64;
        #pragma unroll
        for (int it = 0; it < 16; ++it){
            int lin = it*256 + tid;
            int kk = lin >> 6, d = lin & 63;
            ts[kk][d] = V[((size_t)bh*S_ + k0 + kk)*D_ + d];
        }
        __syncthreads();
        #pragma unroll
        for (int it = 0; it < 16; ++it){
            int lin = it*256 + tid;
            int d = lin >> 6, kk = lin & 63;
            float v = ts[kk][d];
            __nv_bfloat16 h = __float2bfloat16(v);
            __nv_bfloat16 l = __float2bfloat16(v - __bfloat162float(h));
            size_t o = ((size_t)bh*D_ + d)*S_ + k0 + kk;
            g_vthi[o] = h;
            g_vtlo[o] = l;
        }
    }
}

// ---------------- fused attention: no-max softmax + double-buffered K/V ----------------
// Q/K rows: 64 elems stride SQ1=72 (144B). V^T rows: 128 elems stride SV=136 (272B).
#define SQ1   72
#define SV    136
#define F_QH  0
#define F_QL  18432
#define F_BUF 36864
#define BUFSZ 71680          /* KH 18432 + KL 18432 + VH 17408 + VL 17408 */
#define O_KH  0
#define O_KL  18432
#define O_VH  36864
#define O_VL  54272
#define F_IL  180224
#define SMEMF 180736

__global__ __launch_bounds__(256) void fused_attn_kernel(
    const unsigned* __restrict__ mask, const float* __restrict__ adj,
    float* __restrict__ P, float* __restrict__ Out)
{
    extern __shared__ char smem[];
    const unsigned sb = smem_u32(smem);
    const int tid = threadIdx.x, w = tid >> 5, l = tid & 31;
    const int bh = blockIdx.y, b = bh >> 4;
    const int q0 = blockIdx.x * TQ;

    const __nv_bfloat16* kh_g = g_khi + (size_t)bh*S_*D_;
    const __nv_bfloat16* kl_g = g_klo + (size_t)bh*S_*D_;
    const __nv_bfloat16* vh_g = g_vthi + (size_t)bh*D_*S_;
    const __nv_bfloat16* vl_g = g_vtlo + (size_t)bh*D_*S_;

    // prologue: Q hi/lo + tile 0 K/V (one cp.async group)
    {
        const __nv_bfloat16* qh = g_qhi + ((size_t)bh*S_ + q0)*D_;
        const __nv_bfloat16* ql = g_qlo + ((size_t)bh*S_ + q0)*D_;
        #pragma unroll
        for (int it = 0; it < 8; ++it){
            int lin = it*256 + tid;
            int half = lin >> 10, idx = lin & 1023;
            int row = idx >> 3, g = idx & 7;
            cp16(sb + (half ? F_QL : F_QH) + (row*SQ1 + g*8)*2,
                 (half ? ql : qh) + row*D_ + g*8);
        }
        const unsigned bufb = sb + F_BUF;
        #pragma unroll
        for (int it = 0; it < 16; ++it){
            int lin = it*256 + tid;
            int sel = lin >> 10, idx = lin & 1023;
            if (sel < 2){   // K hi/lo: 128 rows x 8 chunks
                int row = idx >> 3, g = idx & 7;
                cp16(bufb + (sel ? O_KL : O_KH) + (row*SQ1 + g*8)*2,
                     (sel ? kl_g : kh_g) + (size_t)row*D_ + g*8);
            } else {        // V hi/lo: 64 d-rows x 16 chunks
                int row = idx >> 4, g = idx & 15;
                cp16(bufb + (sel == 3 ? O_VL : O_VH) + (row*SV + g*8)*2,
                     (sel == 3 ? vl_g : vh_g) + (size_t)row*S_ + g*8);
            }
        }
        CP_COMMIT();
    }

    const int la_row = 16*w + (l & 15);
    const int la_k8  = (l >> 4) * 8;
    const int lb_row = l & 7;
    const int lb_k8  = ((l >> 3) & 1) * 8;
    const int qr = l >> 2;
    const int ci = l & 3;

    float l_run[2] = {0.f, 0.f};
    float oacc[8][4];
    #pragma unroll
    for (int dg = 0; dg < 8; ++dg)
        #pragma unroll
        for (int j = 0; j < 4; ++j) oacc[dg][j] = 0.f;

    for (int kt = 0; kt < NKT; ++kt){
        const int k0 = kt * TK;
        // prefetch next tile into other buffer
        if (kt + 1 < NKT){
            const unsigned bufn = sb + F_BUF + ((kt+1)&1)*BUFSZ;
            const int kn = k0 + TK;
            #pragma unroll
            for (int it = 0; it < 16; ++it){
                int lin = it*256 + tid;
                int sel = lin >> 10, idx = lin & 1023;
                if (sel < 2){
                    int row = idx >> 3, g = idx & 7;
                    cp16(bufn + (sel ? O_KL : O_KH) + (row*SQ1 + g*8)*2,
                         (sel ? kl_g : kh_g) + (size_t)(kn + row)*D_ + g*8);
                } else {
                    int row = idx >> 4, g = idx & 15;
                    cp16(bufn + (sel == 3 ? O_VL : O_VH) + (row*SV + g*8)*2,
                         (sel == 3 ? vl_g : vh_g) + (size_t)row*S_ + kn + g*8);
                }
            }
            CP_COMMIT();
            CP_WAIT(1);      // current tile (+Q on kt==0) has landed
        } else {
            CP_WAIT(0);
        }
        __syncthreads();

        const unsigned buf = sb + F_BUF + (kt&1)*BUFSZ;

        // two 64-col halves: QK -> epilogue -> PV, keeping registers small
        #pragma unroll
        for (int h2 = 0; h2 < 2; ++h2){
            const int kc0 = k0 + 64*h2;

            float acc[8][4];
            #pragma unroll
            for (int nt = 0; nt < 8; ++nt)
                #pragma unroll
                for (int j = 0; j < 4; ++j) acc[nt][j] = 0.f;

            #pragma unroll
            for (int kk = 0; kk < 4; ++kk){
                const int koffA = kk*16 + la_k8;
                unsigned ah0,ah1,ah2,ah3, al0,al1,al2,al3;
                ldsm_x4(ah0,ah1,ah2,ah3, sb + F_QH + (la_row*SQ1 + koffA)*2);
                ldsm_x4(al0,al1,al2,al3, sb + F_QL + (la_row*SQ1 + koffA)*2);
                const int koffB = kk*16 + lb_k8;
                #pragma unroll
                for (int nt = 0; nt < 8; ++nt){
                    const int krow = 64*h2 + 8*nt + lb_row;
                    unsigned bh0,bh1, bl0,bl1;
                    ldsm_x2(bh0,bh1, buf + O_KH + (krow*SQ1 + koffB)*2);
                    ldsm_x2(bl0,bl1, buf + O_KL + (krow*SQ1 + koffB)*2);
                    mma16816(acc[nt], ah0,ah1,ah2,ah3, bh0,bh1);
                    mma16816(acc[nt], ah0,ah1,ah2,ah3, bl0,bl1);
                    mma16816(acc[nt], al0,al1,al2,al3, bh0,bh1);
                }
            }

            // epilogue: u = exp((qk + adj)/8), masked -> 0; no max subtraction
            float e0[8], e1[8], f0[8], f1[8];
            #pragma unroll
            for (int h = 0; h < 2; ++h){
                const int row = 16*w + qr + 8*h;
                const float2* ap = (const float2*)(adj + ((size_t)bh*S_ + q0 + row)*S_ + kc0);
                const uint2*  mp = (const uint2*) (mask + ((size_t)b*S_  + q0 + row)*S_ + kc0);
                float2*       pp = (float2*)(P + ((size_t)bh*S_ + q0 + row)*S_ + kc0);
                float* u0 = h ? f0 : e0;
                float* u1 = h ? f1 : e1;
                float es = 0.f;
                #pragma unroll
                for (int nt = 0; nt < 8; ++nt){
                    float2 a = ap[ci + 4*nt];
                    uint2 mv = mp[ci + 4*nt];
                    float x0 = __expf((acc[nt][2*h]   + a.x) * 0.125f);
                    float x1 = __expf((acc[nt][2*h+1] + a.y) * 0.125f);
                    if (mv.x) x0 = 0.f;
                    if (mv.y) x1 = 0.f;
                    u0[nt] = x0; u1[nt] = x1;
                    es += x0 + x1;
                    pp[ci + 4*nt] = make_float2(x0, x1);
                }
                es += __shfl_xor_sync(0xffffffffu, es, 1);
                es += __shfl_xor_sync(0xffffffffu, es, 2);
                l_run[h] += es;
            }

            // PV: O += u @ V for these 64 k-columns
            #pragma unroll
            for (int kb = 0; kb < 4; ++kb){
                unsigned a0,b0_, a1,b1_, a2,b2_, a3,b3_;
                hilo2(e0[2*kb],   e1[2*kb],   a0, b0_);
                hilo2(f0[2*kb],   f1[2*kb],   a1, b1_);
                hilo2(e0[2*kb+1], e1[2*kb+1], a2, b2_);
                hilo2(f0[2*kb+1], f1[2*kb+1], a3, b3_);
                const int koffB = 64*h2 + kb*16 + lb_k8;
                #pragma unroll
                for (int dg = 0; dg < 8; ++dg){
                    unsigned vh0,vh1, vl0,vl1;
                    ldsm_x2(vh0,vh1, buf + O_VH + ((8*dg + lb_row)*SV + koffB)*2);
                    ldsm_x2(vl0,vl1, buf + O_VL + ((8*dg + lb_row)*SV + koffB)*2);
                    mma16816(oacc[dg], a0,a1,a2,a3, vh0,vh1);
                    mma16816(oacc[dg], a0,a1,a2,a3, vl0,vl1);
                    mma16816(oacc[dg], b0_,b1_,b2_,b3_, vh0,vh1);
                }
            }
        }
        __syncthreads();   // all reads of buf done before it is refilled (kt+2)
    }

    // ---- write O = oacc / l ----
    #pragma unroll
    for (int h = 0; h < 2; ++h){
        const int row = 16*w + qr + 8*h;
        const float inv = 1.0f / l_run[h];
        float2* op = (float2*)(Out + ((size_t)bh*S_ + q0 + row)*D_);
        #pragma unroll
        for (int dg = 0; dg < 8; ++dg)
            op[ci + 4*dg] = make_float2(oacc[dg][2*h]*inv, oacc[dg][2*h+1]*inv);
    }

    // ---- publish 1/l, then scale this CTA's P stripe in place ----
    float* sm_il = (float*)(smem + F_IL);
    if (ci == 0){
        #pragma unroll
        for (int h = 0; h < 2; ++h){
            const int row = 16*w + qr + 8*h;
            sm_il[row] = 1.0f / l_run[h];
        }
    }
    __syncthreads();

    #pragma unroll
    for (int j = 0; j < 16; ++j){
        const int lr = 8*j + w;              // 0..127
        const float il = sm_il[lr];
        float4* pr = (float4*)(P + ((size_t)bh*S_ + q0 + lr)*S_);
        #pragma unroll 4
        for (int c = 0; c < 16; ++c){
            int idx = c*32 + l;              // 512 float4 across the row
            float4 v = pr[idx];
            v.x *= il; v.y *= il; v.z *= il; v.w *= il;
            pr[idx] = v;
        }
    }
}

// ---------------------------------------------------------------------------
extern "C" void kernel_launch(void* const* d_in, const int* in_sizes, int n_in,
                              void* d_out, int out_size) {
    const float*    Q    = (const float*)d_in[0];
    const float*    K    = (const float*)d_in[1];
    const float*    V    = (const float*)d_in[2];
    const unsigned* mask = (const unsigned*)d_in[3];
    const float*    adj  = (const float*)d_in[4];

    float* out = (float*)d_out;                       // (B,H,S,D)
    float* P   = out + (size_t)B_ * H_ * S_ * D_;     // (B,H,S,S)

    cudaFuncSetAttribute(fused_attn_kernel, cudaFuncAttributeMaxDynamicSharedMemorySize, SMEMF);

    prep_kernel<<<dim3(S_/64, BH_, 3), 256>>>(Q, K, V);
    fused_attn_kernel<<<dim3(S_/TQ, BH_), 256, SMEMF>>>(mask, adj, P, out);
}